// round 16
// baseline (speedup 1.0000x reference)
#include <cuda_runtime.h>

// Problem constants (fixed by the reference setup)
#define DE   200          // entity / output dim
#define DR   200          // relation dim
#define DIN  400          // DE + DR
#define NB   4            // num bases
#define KTOT (NB * DIN)   // 1600 rows of the collapsed matvec

#define NTHR 512          // 16 warps
#define NSCAN 64          // scan blocks: blockIdx 0..63 (EARLIEST dispatch), 4-wide
#define NMM  25           // consumer blocks: blockIdx 64..88 (scan-free)
#define NBLK (NSCAN + NMM)   // 89 CTAs total — shorter dispatch tail
#define TARGET NSCAN         // arrivals: scan blocks only (block 0 also zeroes out)
#define KCH  64           // k-rows per consumer block (25*64 = 1600 EXACT)
#define MAXM 1024         // slot capacity (expected ~8 matches)
#define NSPEC 15          // spec warps 1..15 own slots 0..14

// persistent scratch (static device globals — no allocation).
// g_seq: monotonic launch counter (incremented once per launch by releaser).
// g_arr: double-buffered arrive/count word (low16 arrivals, high16 match
//        count). Buffer seq&1 is used this launch; the releaser zeroes the
//        OTHER buffer for the next launch. Padded to separate cache lines.
// g_slot: self-validating: bits[19:64) = seq+1 tag, bits[0:19) = edge index.
__device__ unsigned           g_seq;
__device__ unsigned           g_arr[2][32];
__device__ unsigned long long g_slot[MAXM];

__global__ void __launch_bounds__(NTHR, 1)
fused_kernel(const float* __restrict__ ent,
             const float* __restrict__ relemb,
             const float* __restrict__ basis,
             const float* __restrict__ att,
             const int*   __restrict__ node_id,
             const int*   __restrict__ edge_src,
             const int*   __restrict__ edge_dst,
             const int*   __restrict__ edge_type,
             const int*   __restrict__ rel_index,
             const int*   __restrict__ u_ptr,
             float* __restrict__ out,
             int E) {
    const int tid  = threadIdx.x;
    const int wid  = tid >> 5;
    const int lane = tid & 31;
    const bool is_scan = (blockIdx.x < NSCAN);   // scanners get EARLIEST slots

    const unsigned seq = g_seq;                        // stable this launch
    const unsigned par = seq & 1u;
    const unsigned long long tag = (unsigned long long)(seq + 1u);
    unsigned* arr      = &g_arr[par][0];
    unsigned* arr_next = &g_arr[par ^ 1u][0];

    if (is_scan) {
        // ───────────────────────── scan block ─────────────────────────
        // Scan block 0 (dispatched FIRST) also zeroes the REDG target;
        // its arrival fence publishes the zeroing before the release.
        if (blockIdx.x == 0 && tid < DE) out[tid] = 0.0f;

        // Finder publishes INSTANTLY: slot = (tag<<19)|e — no loads on the
        // finder path, so scan blocks arrive with zero straggler chain.
        auto found = [&](int e) {
            unsigned old = atomicAdd(arr, 1u << 16);
            unsigned p = old >> 16;
            if (p < MAXM)
                *(volatile unsigned long long*)&g_slot[p] =
                    (tag << 19) | (unsigned long long)(unsigned)e;
        };
        auto check4 = [&](int4 v, int base, int u) {
            if (v.x == u) found(base + 0);
            if (v.y == u) found(base + 1);
            if (v.z == u) found(base + 2);
            if (v.w == u) found(base + 3);
        };
        const int sgt = blockIdx.x * NTHR + tid;
        const int SGT = NSCAN * NTHR;
        const int u   = *u_ptr;                        // L1-cached broadcast
        const int nv  = E >> 2;
        const int4* ed4 = (const int4*)edge_dst;
        // 4-wide MLP: all loads issue before any compare; ONE iteration at
        // these sizes (4*SGT = 131072 >= nv = 100000).
        for (int i = sgt; i < nv; i += 4 * SGT) {
            int  i2 = i + SGT,     i3 = i + 2 * SGT,  i4 = i + 3 * SGT;
            bool h2 = i2 < nv;     bool h3 = i3 < nv; bool h4 = i4 < nv;
            int4 v1 = __ldcg(&ed4[i]);
            int4 v2, v3, v4;
            if (h2) v2 = __ldcg(&ed4[i2]);
            if (h3) v3 = __ldcg(&ed4[i3]);
            if (h4) v4 = __ldcg(&ed4[i4]);
            check4(v1, i << 2, u);
            if (h2) check4(v2, i2 << 2, u);
            if (h3) check4(v3, i3 << 2, u);
            if (h4) check4(v4, i4 << 2, u);
        }
        for (int e = (nv << 2) + sgt; e < E; e += SGT) {   // scalar tail
            if (__ldcg(&edge_dst[e]) == u) found(e);
        }
        __syncthreads();
        if (tid == 0) {
            __threadfence();                           // publish finds + zero
            unsigned old = atomicAdd(arr, 1u);
            if ((old & 0xFFFFu) == TARGET - 1) {       // releaser
                *arr_next = 0;                         // next launch's buffer
                __threadfence();
                g_seq = seq + 1u;
            }
        }
        return;                                        // scan blocks exit
    }

    // ──────────────────── consumer block (dispatched LAST) ────────────────
    const int cidx = blockIdx.x - NSCAN;               // 0..24
    const int k0   = cidx * KCH;                       // kmax == KCH exactly

    __shared__ float        sy[KCH];
    __shared__ volatile int s_flag;
    __shared__ volatile int s_cnt;

    // Group 0 (tid < 256) holds the FULL 64-row basis chunk in registers
    // (prefetched pre-release, overlapped with the scan) and later does the
    // single-stage combine -> REDG. Group 1 only spec-consumes.
    const int o = tid;                                 // output idx (tid<256)
    float breg[KCH];
    if (tid < DE) {
        #pragma unroll
        for (int j = 0; j < KCH; j++) {
            breg[j] = __ldcg(&basis[(size_t)(k0 + j) * DE + o]);
        }
    }
    if (tid < KCH) sy[tid] = 0.0f;
    if (tid == 0) { s_flag = 0; s_cnt = 0; }
    __syncthreads();

    // ── spec consume: warp w (1..15) polls slot w-1 from t=0; the meta chain
    //    (edge_src -> node_id -> x) runs DURING the scan. Warp 0/tid0 polls
    //    the arrive word and broadcasts completion via smem. ──
    if (wid == 0) {
        if (tid == 0) {
            unsigned v;
            do { v = *(volatile unsigned*)arr; } while ((v & 0xFFFFu) != TARGET);
            __threadfence();                           // acquire
            s_cnt = (int)(v >> 16);
            __threadfence_block();
            s_flag = 1;
        }
    } else {
        const int m = wid - 1;                         // slot owned by warp
        unsigned long long v;
        bool have = false;
        for (;;) {
            v = *(volatile unsigned long long*)&g_slot[m];
            if ((v >> 19) == tag) { have = true; break; }   // self-validating
            if (s_flag && s_cnt <= m) break;           // will never fill
        }
        if (have) {
            int e  = (int)(v & 0x7FFFFu);
            int s  = __ldcg(&edge_src[e]);             // these issue together
            int ri = __ldcg(&rel_index[e]);
            int ty = __ldcg(&edge_type[e]);
            int nid = __ldcg(&node_id[s]);             // serial hop
            const float* arow = att + (size_t)ty * NB;
            #pragma unroll
            for (int h = 0; h < 2; h++) {
                int kk = lane + h * 32;                // covers 0..63 exactly
                int k = k0 + kk;
                int b = k / DIN;
                int i = k - b * DIN;
                float x = (i < DE)
                    ? __ldcg(&ent[(size_t)nid * DE + i])
                    : __ldcg(&relemb[(size_t)ri * DR + (i - DE)]);
                atomicAdd(&sy[kk], arow[b] * x);
            }
        }
    }
    __syncthreads();

    const int   cnt  = s_cnt;
    const int   cntc = cnt < MAXM ? cnt : MAXM;
    const float inv  = 1.0f / fmaxf((float)cnt, 1.0f);

    if (cntc > NSPEC) {                                // rare (expected cnt≈8)
        const int total = (cntc - NSPEC) * KCH;
        for (int p = tid; p < total; p += NTHR) {
            int mm = NSPEC + p / KCH;
            int kk = p - (mm - NSPEC) * KCH;
            unsigned long long v = g_slot[mm];
            int e  = (int)(v & 0x7FFFFu);
            int s  = __ldcg(&edge_src[e]);
            int ri = __ldcg(&rel_index[e]);
            int ty = __ldcg(&edge_type[e]);
            int nid = __ldcg(&node_id[s]);
            int k = k0 + kk;
            int b = k / DIN;
            int i = k - b * DIN;
            float x = (i < DE)
                ? __ldcg(&ent[(size_t)nid * DE + i])
                : __ldcg(&relemb[(size_t)ri * DR + (i - DE)]);
            atomicAdd(&sy[kk], att[ty * NB + b] * x);
        }
        __syncthreads();
    }

    // single-stage combine: group 0 does the full 64-FMA dot from
    // smem-broadcast sy -> ONE pre-scaled REDG lane per output element.
    if (tid < DE && cntc > 0) {
        float acc = 0.0f;
        #pragma unroll
        for (int j = 0; j < KCH; j++) acc += sy[j] * breg[j];
        atomicAdd(&out[o], acc * inv);                 // fire-and-forget REDG
    }
    // no reset tail: arrive buffer for the next launch zeroed by the
    // releaser; g_seq monotonic; slots invalidated by the seq tag.
}

extern "C" void kernel_launch(void* const* d_in, const int* in_sizes, int n_in,
                              void* d_out, int out_size) {
    const float* ent    = (const float*)d_in[0];  // [100000, 200]
    const float* relemb = (const float*)d_in[1];  // [200, 200]
    const float* basis  = (const float*)d_in[2];  // [4, 400, 200]
    const float* att    = (const float*)d_in[3];  // [400, 4]
    const int* node_id  = (const int*)d_in[4];    // [50000]
    const int* edge_src = (const int*)d_in[5];    // [400000]
    const int* edge_dst = (const int*)d_in[6];    // [400000]
    const int* edge_typ = (const int*)d_in[7];    // [400000]
    const int* rel_idx  = (const int*)d_in[8];    // [400000]
    const int* u_ptr    = (const int*)d_in[9];    // scalar
    float* out = (float*)d_out;                   // [200]

    int E = in_sizes[6];

    fused_kernel<<<NBLK, NTHR>>>(ent, relemb, basis, att,
                                 node_id, edge_src, edge_dst, edge_typ, rel_idx,
                                 u_ptr, out, E);
}